// round 11
// baseline (speedup 1.0000x reference)
#include <cuda_runtime.h>
#include <math.h>
#include <stdint.h>

#define NN 2048
#define NE 32768
#define HD 128
#define CAP 128
#define HPAD 132

// ---------------- scratch (zero at module load; every call restores zeros) ----
__device__ int   g_adj[NN * NN];          // winning (edge+1) per (src,dst), 0 = none
__device__ int   g_wcnt_src[NN];
__device__ int   g_cnt_dst[NN];
__device__ int   g_nb_col[NN * CAP];
__device__ float g_nb_val[NN * CAP];
__device__ int   g_in_edge[NN * CAP];
__device__ float g_A[NN * HD];
__device__ float g_res[NE];
__device__ float g_wgt[NE];
__device__ float g_wm[NE * HD];
__device__ float g_agg[NN * HD];
__device__ float g_meanr[NN];
__device__ unsigned g_bcnt = 0;           // self-resetting arrival counter
__device__ unsigned g_bgen = 0;           // monotonic generation (never reset)

__device__ __forceinline__ void grid_bar(int G) {
    __syncthreads();
    if (threadIdx.x == 0) {
        __threadfence();
        unsigned gen = atomicAdd(&g_bgen, 0u);
        if (atomicAdd(&g_bcnt, 1u) == (unsigned)(G - 1)) {
            atomicExch(&g_bcnt, 0u);
            atomicAdd(&g_bgen, 1u);
        } else {
            int ns = 64;
            while (atomicAdd(&g_bgen, 0u) == gen) {
                __nanosleep(ns);
                if (ns < 2048) ns += ns;
            }
        }
        __threadfence();
    }
    __syncthreads();
}

#define MMA_TF32(c, a0, a1, a2, a3, bb0, bb1)                              \
    asm volatile(                                                          \
        "mma.sync.aligned.m16n8k8.row.col.f32.tf32.tf32.f32 "              \
        "{%0,%1,%2,%3}, {%4,%5,%6,%7}, {%8,%9}, {%0,%1,%2,%3};"            \
        : "+f"((c)[0]), "+f"((c)[1]), "+f"((c)[2]), "+f"((c)[3])           \
        : "r"(a0), "r"(a1), "r"(a2), "r"(a3), "r"(bb0), "r"(bb1))

// 8-warp 64xHD tf32 GEMM over K=128 from smem tile (rows x HPAD) vs global W[k][n].
// Accumulates into c[4][2][4]; warp covers cols [warp*16, warp*16+16).
#define GEMM_K128(xu, W, c, n0, gid, tig)                                          \
    _Pragma("unroll 2")                                                            \
    for (int kt = 0; kt < 16; kt++) {                                              \
        int k0 = kt * 8;                                                           \
        uint32_t bf0[2], bf1[2];                                                   \
        _Pragma("unroll")                                                          \
        for (int nt = 0; nt < 2; nt++) {                                           \
            int n = (n0) + nt * 8 + (gid);                                         \
            bf0[nt] = __float_as_uint(__ldg(&(W)[(k0 + (tig)) * HD + n]));         \
            bf1[nt] = __float_as_uint(__ldg(&(W)[(k0 + (tig) + 4) * HD + n]));     \
        }                                                                          \
        uint32_t a0[4], a1[4], a2[4], a3[4];                                       \
        _Pragma("unroll")                                                          \
        for (int mt = 0; mt < 4; mt++) {                                           \
            int r0 = mt * 16 + (gid);                                              \
            a0[mt] = (xu)[r0 * HPAD + k0 + (tig)];                                 \
            a1[mt] = (xu)[(r0 + 8) * HPAD + k0 + (tig)];                           \
            a2[mt] = (xu)[r0 * HPAD + k0 + (tig) + 4];                             \
            a3[mt] = (xu)[(r0 + 8) * HPAD + k0 + (tig) + 4];                       \
        }                                                                          \
        _Pragma("unroll")                                                          \
        for (int mt = 0; mt < 4; mt++)                                             \
            _Pragma("unroll")                                                      \
            for (int nt = 0; nt < 2; nt++)                                         \
                MMA_TF32(c[mt][nt], a0[mt], a1[mt], a2[mt], a3[mt], bf0[nt], bf1[nt]);\
    }

#define ZERO_C(c)                                                          \
    _Pragma("unroll")                                                      \
    for (int mt = 0; mt < 4; mt++)                                         \
        _Pragma("unroll")                                                  \
        for (int nt = 0; nt < 2; nt++)                                     \
            _Pragma("unroll")                                              \
            for (int q = 0; q < 4; q++) c[mt][nt][q] = 0.0f;

__global__ void __launch_bounds__(256, 2)
k_persist(int G,
          const int* __restrict__ ei,
          const float* __restrict__ dist, const float* __restrict__ conf,
          const float* __restrict__ ang,  const float* __restrict__ dep,
          const float* __restrict__ msgw1, const float* __restrict__ msgb1,
          const float* __restrict__ msgw2, const float* __restrict__ msgb2,
          const float* __restrict__ muw1, const float* __restrict__ mub1,
          const float* __restrict__ muw2, const float* __restrict__ mub2,
          const float* __restrict__ sgw1, const float* __restrict__ sgb1,
          const float* __restrict__ sgw2, const float* __restrict__ sgb2,
          const float* __restrict__ mu,   const float* __restrict__ sigma,
          float* __restrict__ out,        float* __restrict__ out_res) {
    __shared__ float xs[64 * HPAD];
    __shared__ float mr[64];

    int b = blockIdx.x;
    int t = threadIdx.x;
    int warp = t >> 5, lane = t & 31, gid = lane >> 2, tig = lane & 3;
    int n0 = warp * 16;
    int tt = t & 127, hh = t >> 7;
    const uint32_t* xu = (const uint32_t*)xs;

    // ================= P1: adj scatter + dst bucket =================
    for (int e = b * 256 + t; e < NE; e += G * 256) {
        int s = ei[e], d = ei[NE + e];
        atomicMax(&g_adj[s * NN + d], e + 1);
        int q = atomicAdd(&g_cnt_dst[d], 1);
        g_in_edge[d * CAP + q] = e;
    }
    grid_bar(G);

    // ================= P2: winner-bucket fill + nodeA GEMM =================
    for (int e = b * 256 + t; e < NE; e += G * 256) {
        int s = ei[e], d = ei[NE + e];
        if (g_adj[s * NN + d] == e + 1) {
            int p = atomicAdd(&g_wcnt_src[s], 1);
            g_nb_col[s * CAP + p] = d;
            g_nb_val[s * CAP + p] = dist[e];
        }
    }
    for (int tile = b; tile < 32; tile += G) {
        int nb = tile * 64;
        float c[4][2][4];
        ZERO_C(c);
        #pragma unroll 1
        for (int half = 0; half < 2; half++) {
            const float* src = half ? sigma : mu;
            __syncthreads();
            for (int x = hh * 32; x < hh * 32 + 32; x++)
                xs[x * HPAD + tt] = src[(nb + x) * HD + tt];
            __syncthreads();
            const float* W = msgw1 + half * 128 * HD;
            GEMM_K128(xu, W, c, n0, gid, tig);
        }
        #pragma unroll
        for (int nt = 0; nt < 2; nt++) {
            int n = n0 + nt * 8 + 2 * tig;
            float bb0 = __ldg(&msgb1[n]);
            float bb1 = __ldg(&msgb1[n + 1]);
            #pragma unroll
            for (int mt = 0; mt < 4; mt++) {
                int m0 = nb + mt * 16 + gid;
                int m1 = m0 + 8;
                *(float2*)&g_A[m0 * HD + n] = make_float2(c[mt][nt][0] + bb0, c[mt][nt][1] + bb1);
                *(float2*)&g_A[m1 * HD + n] = make_float2(c[mt][nt][2] + bb0, c[mt][nt][3] + bb1);
            }
        }
        __syncthreads();
    }
    grid_bar(G);

    // ================= P3: residuals (2 edges/warp) + edge GEMM =================
    {
        int l = lane & 15;
        for (int p = b * 8 + warp; p < NE / 2; p += G * 8) {
            int e = p * 2 + (lane >> 4);
            int s = ei[e], d = ei[NE + e];
            int nw = g_wcnt_src[s];
            int base = s * CAP;
            float sum = 0.0f; int cnt = 0;
            for (int i = l; i < nw; i += 16) {
                int B   = g_nb_col[base + i];
                float dab = g_nb_val[base + i];
                int idx = g_adj[B * NN + d];
                if (idx > 0) { sum += dab + dist[idx - 1]; cnt++; }
            }
            #pragma unroll
            for (int o = 8; o > 0; o >>= 1) {
                sum += __shfl_down_sync(0xffffffffu, sum, o, 16);
                cnt += __shfl_down_sync(0xffffffffu, cnt, o, 16);
            }
            if (l == 0) {
                float dac = dist[e];
                float mean = (cnt > 0) ? (sum / (float)cnt) : dac;
                float r = fabsf(dac - mean);
                g_res[e] = r;
                g_wgt[e] = expf(-r);
                out_res[e] = r;
            }
        }
    }
    {
        float wf0 = msgw1[(256) * HD + tt];
        float wf1 = msgw1[(257) * HD + tt];
        float wf2 = msgw1[(258) * HD + tt];
        float wf3 = msgw1[(259) * HD + tt];
        for (int tile = b; tile < 512; tile += G) {
            int eb = tile * 64;
            __syncthreads();
            #pragma unroll 4
            for (int x = hh * 32; x < hh * 32 + 32; x++) {
                int e = eb + x;
                int s = ei[e];
                float v = g_A[s * HD + tt]
                        + dist[e] * wf0 + conf[e] * wf1 + ang[e] * wf2 + dep[e] * wf3;
                xs[x * HPAD + tt] = fmaxf(v, 0.0f);
            }
            __syncthreads();
            float c[4][2][4];
            ZERO_C(c);
            GEMM_K128(xu, msgw2, c, n0, gid, tig);
            #pragma unroll
            for (int nt = 0; nt < 2; nt++) {
                int n = n0 + nt * 8 + 2 * tig;
                float bb0 = __ldg(&msgb2[n]);
                float bb1 = __ldg(&msgb2[n + 1]);
                #pragma unroll
                for (int mt = 0; mt < 4; mt++) {
                    int e0 = eb + mt * 16 + gid;
                    int e1 = e0 + 8;
                    *(float2*)&g_wm[e0 * HD + n] = make_float2(c[mt][nt][0] + bb0, c[mt][nt][1] + bb1);
                    *(float2*)&g_wm[e1 * HD + n] = make_float2(c[mt][nt][2] + bb0, c[mt][nt][3] + bb1);
                }
            }
        }
    }
    grid_bar(G);

    // ================= P4: aggregation + adj/src-count cleanup =================
    for (int e = b * 256 + t; e < NE; e += G * 256) {
        int s = ei[e], d = ei[NE + e];
        g_adj[s * NN + d] = 0;
    }
    for (int i = b * 256 + t; i < NN; i += G * 256) g_wcnt_src[i] = 0;
    for (int n = b * 2 + hh; n < NN; n += 2 * G) {
        int cnt = g_cnt_dst[n];
        int base = n * CAP;
        float acc = 0.0f, ws = 0.0f, rs = 0.0f;
        for (int i = 0; i < cnt; i++) {
            int e = g_in_edge[base + i];
            float w = g_wgt[e];
            acc += g_wm[e * HD + tt] * w;
            ws  += w;
            rs  += g_res[e];
        }
        g_agg[n * HD + tt] = acc / fmaxf(ws, 1e-8f);
        if (tt == 0) g_meanr[n] = rs / fmaxf((float)cnt, 1.0f);
    }
    grid_bar(G);

    // ================= P5: node MLPs + dst-count cleanup =================
    for (int i = b * 256 + t; i < NN; i += G * 256) g_cnt_dst[i] = 0;

    for (int item = b; item < 64; item += G) {
        int path = item & 1;
        int nb = (item >> 1) * 64;

        __syncthreads();
        for (int x = hh * 32; x < hh * 32 + 32; x++)
            xs[x * HPAD + tt] = g_agg[(nb + x) * HD + tt];
        if (t < 64) mr[t] = g_meanr[nb + t];
        __syncthreads();

        const float* W1 = path ? sgw1 : muw1;
        const float* B1 = path ? sgb1 : mub1;
        const float* W2 = path ? sgw2 : muw2;
        const float* B2 = path ? sgb2 : mub2;

        float c[4][2][4];
        ZERO_C(c);
        GEMM_K128(xu, W1, c, n0, gid, tig);
        __syncthreads();

        #pragma unroll
        for (int nt = 0; nt < 2; nt++) {
            int n = n0 + nt * 8 + 2 * tig;
            float bb0 = __ldg(&B1[n]);
            float bb1 = __ldg(&B1[n + 1]);
            float wl0 = 0.0f, wl1 = 0.0f;
            if (path) { wl0 = __ldg(&sgw1[128 * HD + n]); wl1 = __ldg(&sgw1[128 * HD + n + 1]); }
            #pragma unroll
            for (int mt = 0; mt < 4; mt++) {
                int m0 = mt * 16 + gid;
                int m1 = m0 + 8;
                float e0 = path ? mr[m0] : 0.0f;
                float e1 = path ? mr[m1] : 0.0f;
                xs[m0 * HPAD + n]     = fmaxf(c[mt][nt][0] + bb0 + e0 * wl0, 0.0f);
                xs[m0 * HPAD + n + 1] = fmaxf(c[mt][nt][1] + bb1 + e0 * wl1, 0.0f);
                xs[m1 * HPAD + n]     = fmaxf(c[mt][nt][2] + bb0 + e1 * wl0, 0.0f);
                xs[m1 * HPAD + n + 1] = fmaxf(c[mt][nt][3] + bb1 + e1 * wl1, 0.0f);
            }
        }
        __syncthreads();

        ZERO_C(c);
        GEMM_K128(xu, W2, c, n0, gid, tig);

        #pragma unroll
        for (int nt = 0; nt < 2; nt++) {
            int n = n0 + nt * 8 + 2 * tig;
            float bb0 = __ldg(&B2[n]);
            float bb1 = __ldg(&B2[n + 1]);
            #pragma unroll
            for (int mt = 0; mt < 4; mt++) {
                int m0 = nb + mt * 16 + gid;
                int m1 = m0 + 8;
                float v00 = c[mt][nt][0] + bb0, v01 = c[mt][nt][1] + bb1;
                float v10 = c[mt][nt][2] + bb0, v11 = c[mt][nt][3] + bb1;
                if (!path) {
                    float2 mu0 = *(const float2*)&mu[m0 * HD + n];
                    float2 mu1 = *(const float2*)&mu[m1 * HD + n];
                    *(float2*)&out[m0 * HD + n] = make_float2(mu0.x + v00, mu0.y + v01);
                    *(float2*)&out[m1 * HD + n] = make_float2(mu1.x + v10, mu1.y + v11);
                } else {
                    float s00 = fmaxf(v00, 0.0f) + log1pf(expf(-fabsf(v00)));
                    float s01 = fmaxf(v01, 0.0f) + log1pf(expf(-fabsf(v01)));
                    float s10 = fmaxf(v10, 0.0f) + log1pf(expf(-fabsf(v10)));
                    float s11 = fmaxf(v11, 0.0f) + log1pf(expf(-fabsf(v11)));
                    *(float2*)&out[NN * HD + m0 * HD + n] = make_float2(s00, s01);
                    *(float2*)&out[NN * HD + m1 * HD + n] = make_float2(s10, s11);
                }
            }
        }
        __syncthreads();
    }
}

// ---------------- launch: ONE kernel ----------------
extern "C" void kernel_launch(void* const* d_in, const int* in_sizes, int n_in,
                              void* d_out, int out_size) {
    const float* mu    = (const float*)d_in[0];
    const float* sigma = (const float*)d_in[1];
    const int*   ei    = (const int*)d_in[2];
    const float* dist  = (const float*)d_in[3];
    const float* conf  = (const float*)d_in[4];
    const float* ang   = (const float*)d_in[5];
    const float* dep   = (const float*)d_in[6];
    const float* msgw1 = (const float*)d_in[7];
    const float* msgb1 = (const float*)d_in[8];
    const float* msgw2 = (const float*)d_in[9];
    const float* msgb2 = (const float*)d_in[10];
    const float* muw1  = (const float*)d_in[11];
    const float* mub1  = (const float*)d_in[12];
    const float* muw2  = (const float*)d_in[13];
    const float* mub2  = (const float*)d_in[14];
    const float* sgw1  = (const float*)d_in[15];
    const float* sgb1  = (const float*)d_in[16];
    const float* sgw2  = (const float*)d_in[17];
    const float* sgb2  = (const float*)d_in[18];
    float* out = (float*)d_out;
    float* out_res = out + 2 * NN * HD;

    static int G = 0;
    if (G == 0) {
        int dev = 0, sms = 0, bpm = 0;
        cudaGetDevice(&dev);
        cudaDeviceGetAttribute(&sms, cudaDevAttrMultiProcessorCount, dev);
        cudaOccupancyMaxActiveBlocksPerMultiprocessor(&bpm, k_persist, 256, 0);
        if (sms <= 0) sms = 148;
        if (bpm <= 0) bpm = 1;
        G = sms * bpm;
    }

    k_persist<<<G, 256>>>(G, ei, dist, conf, ang, dep,
                          msgw1, msgb1, msgw2, msgb2,
                          muw1, mub1, muw2, mub2,
                          sgw1, sgb1, sgw2, sgb2,
                          mu, sigma, out, out_res);
}

// round 12
// speedup vs baseline: 1.0004x; 1.0004x over previous
#include <cuda_runtime.h>
#include <math.h>
#include <stdint.h>

#define NN 2048
#define NE 32768
#define HD 128
#define CAP 128
#define HPAD 132

// ---------------- scratch (zero at module load; every call restores zeros) ----
__device__ int   g_adj[NN * NN];          // winning (edge+1) per (src,dst), 0 = none
__device__ int   g_wcnt_src[NN];
__device__ int   g_cnt_dst[NN];
__device__ int   g_nb_col[NN * CAP];
__device__ float g_nb_val[NN * CAP];
__device__ int   g_in_edge[NN * CAP];
__device__ float g_A[NN * HD];
__device__ float g_res[NE];
__device__ float g_wgt[NE];
__device__ float g_wm[NE * HD];
__device__ float g_agg[NN * HD];
__device__ float g_meanr[NN];
__device__ unsigned g_bcnt = 0;           // self-resetting arrival counter
__device__ unsigned g_bgen = 0;           // monotonic generation (never reset)

// Grid barrier: arrival = one atomicAdd per block; WAKE = volatile LOAD
// (same-address loads broadcast at L2; atomic-RMW polling serializes and
// cost ~10us/barrier in R11).
__device__ __forceinline__ void grid_bar(int G) {
    __syncthreads();
    if (threadIdx.x == 0) {
        __threadfence();
        unsigned gen = *(volatile unsigned*)&g_bgen;   // read BEFORE arrival (safe: gen can't advance until we arrive)
        if (atomicAdd(&g_bcnt, 1u) == (unsigned)(G - 1)) {
            atomicExch(&g_bcnt, 0u);
            __threadfence();
            atomicAdd(&g_bgen, 1u);
        } else {
            while (*(volatile unsigned*)&g_bgen == gen) __nanosleep(128);
        }
        __threadfence();
    }
    __syncthreads();
}

#define MMA_TF32(c, a0, a1, a2, a3, bb0, bb1)                              \
    asm volatile(                                                          \
        "mma.sync.aligned.m16n8k8.row.col.f32.tf32.tf32.f32 "              \
        "{%0,%1,%2,%3}, {%4,%5,%6,%7}, {%8,%9}, {%0,%1,%2,%3};"            \
        : "+f"((c)[0]), "+f"((c)[1]), "+f"((c)[2]), "+f"((c)[3])           \
        : "r"(a0), "r"(a1), "r"(a2), "r"(a3), "r"(bb0), "r"(bb1))

#define GEMM_K128(xu, W, c, n0, gid, tig)                                          \
    _Pragma("unroll 2")                                                            \
    for (int kt = 0; kt < 16; kt++) {                                              \
        int k0 = kt * 8;                                                           \
        uint32_t bf0[2], bf1[2];                                                   \
        _Pragma("unroll")                                                          \
        for (int nt = 0; nt < 2; nt++) {                                           \
            int n = (n0) + nt * 8 + (gid);                                         \
            bf0[nt] = __float_as_uint(__ldg(&(W)[(k0 + (tig)) * HD + n]));         \
            bf1[nt] = __float_as_uint(__ldg(&(W)[(k0 + (tig) + 4) * HD + n]));     \
        }                                                                          \
        uint32_t a0[4], a1[4], a2[4], a3[4];                                       \
        _Pragma("unroll")                                                          \
        for (int mt = 0; mt < 4; mt++) {                                           \
            int r0 = mt * 16 + (gid);                                              \
            a0[mt] = (xu)[r0 * HPAD + k0 + (tig)];                                 \
            a1[mt] = (xu)[(r0 + 8) * HPAD + k0 + (tig)];                           \
            a2[mt] = (xu)[r0 * HPAD + k0 + (tig) + 4];                             \
            a3[mt] = (xu)[(r0 + 8) * HPAD + k0 + (tig) + 4];                       \
        }                                                                          \
        _Pragma("unroll")                                                          \
        for (int mt = 0; mt < 4; mt++)                                             \
            _Pragma("unroll")                                                      \
            for (int nt = 0; nt < 2; nt++)                                         \
                MMA_TF32(c[mt][nt], a0[mt], a1[mt], a2[mt], a3[mt], bf0[nt], bf1[nt]);\
    }

#define ZERO_C(c)                                                          \
    _Pragma("unroll")                                                      \
    for (int mt = 0; mt < 4; mt++)                                         \
        _Pragma("unroll")                                                  \
        for (int nt = 0; nt < 2; nt++)                                     \
            _Pragma("unroll")                                              \
            for (int q = 0; q < 4; q++) c[mt][nt][q] = 0.0f;

__global__ void __launch_bounds__(256, 2)
k_persist(int G,
          const int* __restrict__ ei,
          const float* __restrict__ dist, const float* __restrict__ conf,
          const float* __restrict__ ang,  const float* __restrict__ dep,
          const float* __restrict__ msgw1, const float* __restrict__ msgb1,
          const float* __restrict__ msgw2, const float* __restrict__ msgb2,
          const float* __restrict__ muw1, const float* __restrict__ mub1,
          const float* __restrict__ muw2, const float* __restrict__ mub2,
          const float* __restrict__ sgw1, const float* __restrict__ sgb1,
          const float* __restrict__ sgw2, const float* __restrict__ sgb2,
          const float* __restrict__ mu,   const float* __restrict__ sigma,
          float* __restrict__ out,        float* __restrict__ out_res) {
    __shared__ float xs[64 * HPAD];
    __shared__ float mr[64];

    int b = blockIdx.x;
    int t = threadIdx.x;
    int warp = t >> 5, lane = t & 31, gid = lane >> 2, tig = lane & 3;
    int n0 = warp * 16;
    int tt = t & 127, hh = t >> 7;
    const uint32_t* xu = (const uint32_t*)xs;

    // ===== P1: scatter+dst bucket (blocks < G-32)  ||  nodeA GEMM (top 32 blocks) =====
    if (b < G - 32) {
        for (int e = b * 256 + t; e < NE; e += (G - 32) * 256) {
            int s = ei[e], d = ei[NE + e];
            atomicMax(&g_adj[s * NN + d], e + 1);
            int q = atomicAdd(&g_cnt_dst[d], 1);
            g_in_edge[d * CAP + q] = e;
        }
    } else {
        int nb = (b - (G - 32)) * 64;
        float c[4][2][4];
        ZERO_C(c);
        #pragma unroll 1
        for (int half = 0; half < 2; half++) {
            const float* src = half ? sigma : mu;
            __syncthreads();
            for (int x = hh * 32; x < hh * 32 + 32; x++)
                xs[x * HPAD + tt] = src[(nb + x) * HD + tt];
            __syncthreads();
            const float* W = msgw1 + half * 128 * HD;
            GEMM_K128(xu, W, c, n0, gid, tig);
        }
        #pragma unroll
        for (int nt = 0; nt < 2; nt++) {
            int n = n0 + nt * 8 + 2 * tig;
            float bb0 = __ldg(&msgb1[n]);
            float bb1 = __ldg(&msgb1[n + 1]);
            #pragma unroll
            for (int mt = 0; mt < 4; mt++) {
                int m0 = nb + mt * 16 + gid;
                int m1 = m0 + 8;
                *(float2*)&g_A[m0 * HD + n] = make_float2(c[mt][nt][0] + bb0, c[mt][nt][1] + bb1);
                *(float2*)&g_A[m1 * HD + n] = make_float2(c[mt][nt][2] + bb0, c[mt][nt][3] + bb1);
            }
        }
    }
    grid_bar(G);

    // ===== P2: winner-bucket fill (blocks < 64)  ||  edge GEMM (blocks >= 64) =====
    if (b < 64) {
        for (int e = b * 256 + t; e < NE; e += 64 * 256) {
            int s = ei[e], d = ei[NE + e];
            if (g_adj[s * NN + d] == e + 1) {
                int p = atomicAdd(&g_wcnt_src[s], 1);
                g_nb_col[s * CAP + p] = d;
                g_nb_val[s * CAP + p] = dist[e];
            }
        }
    } else {
        float wf0 = msgw1[(256) * HD + tt];
        float wf1 = msgw1[(257) * HD + tt];
        float wf2 = msgw1[(258) * HD + tt];
        float wf3 = msgw1[(259) * HD + tt];
        for (int tile = b - 64; tile < 512; tile += G - 64) {
            int eb = tile * 64;
            __syncthreads();
            #pragma unroll 4
            for (int x = hh * 32; x < hh * 32 + 32; x++) {
                int e = eb + x;
                int s = ei[e];
                float v = g_A[s * HD + tt]
                        + dist[e] * wf0 + conf[e] * wf1 + ang[e] * wf2 + dep[e] * wf3;
                xs[x * HPAD + tt] = fmaxf(v, 0.0f);
            }
            __syncthreads();
            float c[4][2][4];
            ZERO_C(c);
            GEMM_K128(xu, msgw2, c, n0, gid, tig);
            #pragma unroll
            for (int nt = 0; nt < 2; nt++) {
                int n = n0 + nt * 8 + 2 * tig;
                float bb0 = __ldg(&msgb2[n]);
                float bb1 = __ldg(&msgb2[n + 1]);
                #pragma unroll
                for (int mt = 0; mt < 4; mt++) {
                    int e0 = eb + mt * 16 + gid;
                    int e1 = e0 + 8;
                    *(float2*)&g_wm[e0 * HD + n] = make_float2(c[mt][nt][0] + bb0, c[mt][nt][1] + bb1);
                    *(float2*)&g_wm[e1 * HD + n] = make_float2(c[mt][nt][2] + bb0, c[mt][nt][3] + bb1);
                }
            }
        }
    }
    grid_bar(G);

    // ===== P3: residuals, 2 edges/warp (all blocks) =====
    {
        int l = lane & 15;
        for (int p = b * 8 + warp; p < NE / 2; p += G * 8) {
            int e = p * 2 + (lane >> 4);
            int s = ei[e], d = ei[NE + e];
            int nw = g_wcnt_src[s];
            int base = s * CAP;
            float sum = 0.0f; int cnt = 0;
            for (int i = l; i < nw; i += 16) {
                int B   = g_nb_col[base + i];
                float dab = g_nb_val[base + i];
                int idx = g_adj[B * NN + d];
                if (idx > 0) { sum += dab + dist[idx - 1]; cnt++; }
            }
            #pragma unroll
            for (int o = 8; o > 0; o >>= 1) {
                sum += __shfl_down_sync(0xffffffffu, sum, o, 16);
                cnt += __shfl_down_sync(0xffffffffu, cnt, o, 16);
            }
            if (l == 0) {
                float dac = dist[e];
                float mean = (cnt > 0) ? (sum / (float)cnt) : dac;
                float r = fabsf(dac - mean);
                g_res[e] = r;
                g_wgt[e] = expf(-r);
                out_res[e] = r;
            }
        }
    }
    grid_bar(G);

    // ===== P4: aggregation + adj/src-count cleanup =====
    for (int e = b * 256 + t; e < NE; e += G * 256) {
        int s = ei[e], d = ei[NE + e];
        g_adj[s * NN + d] = 0;
    }
    for (int i = b * 256 + t; i < NN; i += G * 256) g_wcnt_src[i] = 0;
    for (int n = b * 2 + hh; n < NN; n += 2 * G) {
        int cnt = g_cnt_dst[n];
        int base = n * CAP;
        float acc = 0.0f, ws = 0.0f, rs = 0.0f;
        for (int i = 0; i < cnt; i++) {
            int e = g_in_edge[base + i];
            float w = g_wgt[e];
            acc += g_wm[e * HD + tt] * w;
            ws  += w;
            rs  += g_res[e];
        }
        g_agg[n * HD + tt] = acc / fmaxf(ws, 1e-8f);
        if (tt == 0) g_meanr[n] = rs / fmaxf((float)cnt, 1.0f);
    }
    grid_bar(G);

    // ===== P5: node MLPs + dst-count cleanup =====
    for (int i = b * 256 + t; i < NN; i += G * 256) g_cnt_dst[i] = 0;

    for (int item = b; item < 64; item += G) {
        int path = item & 1;
        int nb = (item >> 1) * 64;

        __syncthreads();
        for (int x = hh * 32; x < hh * 32 + 32; x++)
            xs[x * HPAD + tt] = g_agg[(nb + x) * HD + tt];
        if (t < 64) mr[t] = g_meanr[nb + t];
        __syncthreads();

        const float* W1 = path ? sgw1 : muw1;
        const float* B1 = path ? sgb1 : mub1;
        const float* W2 = path ? sgw2 : muw2;
        const float* B2 = path ? sgb2 : mub2;

        float c[4][2][4];
        ZERO_C(c);
        GEMM_K128(xu, W1, c, n0, gid, tig);
        __syncthreads();

        #pragma unroll
        for (int nt = 0; nt < 2; nt++) {
            int n = n0 + nt * 8 + 2 * tig;
            float bb0 = __ldg(&B1[n]);
            float bb1 = __ldg(&B1[n + 1]);
            float wl0 = 0.0f, wl1 = 0.0f;
            if (path) { wl0 = __ldg(&sgw1[128 * HD + n]); wl1 = __ldg(&sgw1[128 * HD + n + 1]); }
            #pragma unroll
            for (int mt = 0; mt < 4; mt++) {
                int m0 = mt * 16 + gid;
                int m1 = m0 + 8;
                float e0 = path ? mr[m0] : 0.0f;
                float e1 = path ? mr[m1] : 0.0f;
                xs[m0 * HPAD + n]     = fmaxf(c[mt][nt][0] + bb0 + e0 * wl0, 0.0f);
                xs[m0 * HPAD + n + 1] = fmaxf(c[mt][nt][1] + bb1 + e0 * wl1, 0.0f);
                xs[m1 * HPAD + n]     = fmaxf(c[mt][nt][2] + bb0 + e1 * wl0, 0.0f);
                xs[m1 * HPAD + n + 1] = fmaxf(c[mt][nt][3] + bb1 + e1 * wl1, 0.0f);
            }
        }
        __syncthreads();

        ZERO_C(c);
        GEMM_K128(xu, W2, c, n0, gid, tig);

        #pragma unroll
        for (int nt = 0; nt < 2; nt++) {
            int n = n0 + nt * 8 + 2 * tig;
            float bb0 = __ldg(&B2[n]);
            float bb1 = __ldg(&B2[n + 1]);
            #pragma unroll
            for (int mt = 0; mt < 4; mt++) {
                int m0 = nb + mt * 16 + gid;
                int m1 = m0 + 8;
                float v00 = c[mt][nt][0] + bb0, v01 = c[mt][nt][1] + bb1;
                float v10 = c[mt][nt][2] + bb0, v11 = c[mt][nt][3] + bb1;
                if (!path) {
                    float2 mu0 = *(const float2*)&mu[m0 * HD + n];
                    float2 mu1 = *(const float2*)&mu[m1 * HD + n];
                    *(float2*)&out[m0 * HD + n] = make_float2(mu0.x + v00, mu0.y + v01);
                    *(float2*)&out[m1 * HD + n] = make_float2(mu1.x + v10, mu1.y + v11);
                } else {
                    float s00 = fmaxf(v00, 0.0f) + log1pf(expf(-fabsf(v00)));
                    float s01 = fmaxf(v01, 0.0f) + log1pf(expf(-fabsf(v01)));
                    float s10 = fmaxf(v10, 0.0f) + log1pf(expf(-fabsf(v10)));
                    float s11 = fmaxf(v11, 0.0f) + log1pf(expf(-fabsf(v11)));
                    *(float2*)&out[NN * HD + m0 * HD + n] = make_float2(s00, s01);
                    *(float2*)&out[NN * HD + m1 * HD + n] = make_float2(s10, s11);
                }
            }
        }
        __syncthreads();
    }
}

// ---------------- launch: ONE kernel ----------------
extern "C" void kernel_launch(void* const* d_in, const int* in_sizes, int n_in,
                              void* d_out, int out_size) {
    const float* mu    = (const float*)d_in[0];
    const float* sigma = (const float*)d_in[1];
    const int*   ei    = (const int*)d_in[2];
    const float* dist  = (const float*)d_in[3];
    const float* conf  = (const float*)d_in[4];
    const float* ang   = (const float*)d_in[5];
    const float* dep   = (const float*)d_in[6];
    const float* msgw1 = (const float*)d_in[7];
    const float* msgb1 = (const float*)d_in[8];
    const float* msgw2 = (const float*)d_in[9];
    const float* msgb2 = (const float*)d_in[10];
    const float* muw1  = (const float*)d_in[11];
    const float* mub1  = (const float*)d_in[12];
    const float* muw2  = (const float*)d_in[13];
    const float* mub2  = (const float*)d_in[14];
    const float* sgw1  = (const float*)d_in[15];
    const float* sgb1  = (const float*)d_in[16];
    const float* sgw2  = (const float*)d_in[17];
    const float* sgb2  = (const float*)d_in[18];
    float* out = (float*)d_out;
    float* out_res = out + 2 * NN * HD;

    static int G = 0;
    if (G == 0) {
        int dev = 0, sms = 0, bpm = 0;
        cudaGetDevice(&dev);
        cudaDeviceGetAttribute(&sms, cudaDevAttrMultiProcessorCount, dev);
        cudaOccupancyMaxActiveBlocksPerMultiprocessor(&bpm, k_persist, 256, 0);
        if (sms <= 0) sms = 148;
        if (bpm <= 0) bpm = 1;
        G = sms * bpm;
        if (G < 128) G = 128;   // role-split assumes G >= 96; practical floor
    }

    k_persist<<<G, 256>>>(G, ei, dist, conf, ang, dep,
                          msgw1, msgb1, msgw2, msgb2,
                          muw1, mub1, muw2, mub2,
                          sgw1, sgb1, sgw2, sgb2,
                          mu, sigma, out, out_res);
}